// round 4
// baseline (speedup 1.0000x reference)
#include <cuda_runtime.h>
#include <cstdint>

#define NN    4001
#define TILE  128
#define NH    96
#define NTHREADS 256

// shared layout (floats): sEX[NH][TILE] | sEY[NH][TILE] | sh[NH*3]
#define SMEM_FLOATS (2 * NH * TILE + NH * 3)
#define SMEM_BYTES  (SMEM_FLOATS * 4)

__device__ __forceinline__ unsigned long long pack2(float lo, float hi) {
    unsigned long long r;
    asm("mov.b64 %0, {%1, %2};" : "=l"(r) : "f"(lo), "f"(hi));
    return r;
}

__device__ __forceinline__ void unpack2(float& lo, float& hi, unsigned long long v) {
    asm("mov.b64 {%0, %1}, %2;" : "=f"(lo), "=f"(hi) : "l"(v));
}

__device__ __forceinline__ unsigned long long fma2(unsigned long long a,
                                                   unsigned long long b,
                                                   unsigned long long c) {
    unsigned long long d;
    asm("fma.rn.f32x2 %0, %1, %2, %3;" : "=l"(d) : "l"(a), "l"(b), "l"(c));
    return d;
}

__global__ __launch_bounds__(NTHREADS, 2)
void phc_kernel(const float* __restrict__ holes,
                const float* __restrict__ Tp,
                float* __restrict__ out) {
    extern __shared__ float smem[];
    float* sEX = smem;                 // [NH][TILE]
    float* sEY = smem + NH * TILE;     // [NH][TILE]
    float* sh  = smem + 2 * NH * TILE; // [NH*3]

    const int tid = threadIdx.x;
    const int i0 = blockIdx.y * TILE;  // x (row) axis
    const int j0 = blockIdx.x * TILE;  // y (col) axis

    // stage hole params
    for (int t = tid; t < NH * 3; t += NTHREADS) sh[t] = holes[t];
    __syncthreads();

    // Each CTA builds its separable factor slices:
    //   sEX[h][ii] = exp(-(x_{i0+ii} - x0_h)^2 / (2 s^2))
    //   sEY[h][jj] = exp(-(y_{j0+jj} - y0_h)^2 / (2 s^2))
    const float step = 20.0f / 4000.0f;
    for (int idx = tid; idx < NH * TILE; idx += NTHREADS) {
        int h  = idx >> 7;        // /TILE
        int ii = idx & (TILE - 1);
        float x0 = sh[h * 3 + 0];
        float y0 = sh[h * 3 + 1];
        float sg = sh[h * 3 + 2];
        float c  = -0.5f / (sg * sg);
        float xi = fmaf((float)(i0 + ii), step, -10.0f);
        float yj = fmaf((float)(j0 + ii), step, -10.0f);
        float dx = xi - x0;
        float dy = yj - y0;
        sEX[idx] = __expf(c * dx * dx);
        sEY[idx] = __expf(c * dy * dy);
    }
    __syncthreads();

    // 8x8 micro-tile per thread; 16x16 threads -> 128x128 tile
    const int tx = tid & 15;   // col group
    const int ty = tid >> 4;   // row group

    unsigned long long acc[8][4];
    #pragma unroll
    for (int r = 0; r < 8; ++r)
        #pragma unroll
        for (int c = 0; c < 4; ++c) acc[r][c] = 0ull;

    const float* exBase = sEX + ty * 8;
    const float* eyBase = sEY + tx * 8;

    #pragma unroll 2
    for (int h = 0; h < NH; ++h) {
        float4 a0 = *(const float4*)(exBase + h * TILE);
        float4 a1 = *(const float4*)(exBase + h * TILE + 4);
        float4 b0 = *(const float4*)(eyBase + h * TILE);
        float4 b1 = *(const float4*)(eyBase + h * TILE + 4);

        unsigned long long bp[4];
        bp[0] = pack2(b0.x, b0.y);
        bp[1] = pack2(b0.z, b0.w);
        bp[2] = pack2(b1.x, b1.y);
        bp[3] = pack2(b1.z, b1.w);

        float ax[8] = {a0.x, a0.y, a0.z, a0.w, a1.x, a1.y, a1.z, a1.w};

        #pragma unroll
        for (int r = 0; r < 8; ++r) {
            unsigned long long ad = pack2(ax[r], ax[r]);
            #pragma unroll
            for (int c = 0; c < 4; ++c)
                acc[r][c] = fma2(ad, bp[c], acc[r][c]);
        }
    }

    // epilogue: sigmoid((Z - 0.5)/T) and store (scalar stores: row stride
    // 4001 floats means float4/float2 alignment does not hold for most rows)
    const float invT = __fdividef(1.0f, Tp[0]);

    #pragma unroll
    for (int r = 0; r < 8; ++r) {
        int gi = i0 + ty * 8 + r;
        if (gi >= NN) break;
        float z[8];
        #pragma unroll
        for (int c = 0; c < 4; ++c) unpack2(z[2 * c], z[2 * c + 1], acc[r][c]);

        int gj = j0 + tx * 8;
        float* orow = out + (size_t)gi * NN + gj;
        #pragma unroll
        for (int c = 0; c < 8; ++c) {
            if (gj + c < NN) {
                float e = __expf((0.5f - z[c]) * invT);
                orow[c] = __fdividef(1.0f, 1.0f + e);
            }
        }
    }
}

extern "C" void kernel_launch(void* const* d_in, const int* in_sizes, int n_in,
                              void* d_out, int out_size) {
    const float* holes = (const float*)d_in[0];
    const float* T     = (const float*)d_in[1];
    float* out         = (float*)d_out;

    cudaFuncSetAttribute(phc_kernel,
                         cudaFuncAttributeMaxDynamicSharedMemorySize, SMEM_BYTES);

    dim3 grid((NN + TILE - 1) / TILE, (NN + TILE - 1) / TILE);
    phc_kernel<<<grid, NTHREADS, SMEM_BYTES>>>(holes, T, out);
}

// round 6
// speedup vs baseline: 1.3370x; 1.3370x over previous
#include <cuda_runtime.h>
#include <cstdint>

#define NN    4001
#define TILE  128
#define NH    96
#define NT2   512

// precomputed separable factors (3 MB total, lives in L2)
__device__ float EXg[NH * NN];
__device__ float EYg[NH * NN];

#define SMEM_FLOATS (2 * NH * TILE)
#define SMEM_BYTES  (SMEM_FLOATS * 4)

__device__ __forceinline__ unsigned long long pack2(float lo, float hi) {
    unsigned long long r;
    asm("mov.b64 %0, {%1, %2};" : "=l"(r) : "f"(lo), "f"(hi));
    return r;
}
__device__ __forceinline__ void unpack2(float& lo, float& hi, unsigned long long v) {
    asm("mov.b64 {%0, %1}, %2;" : "=f"(lo), "=f"(hi) : "l"(v));
}
__device__ __forceinline__ unsigned long long fma2(unsigned long long a,
                                                   unsigned long long b,
                                                   unsigned long long c) {
    unsigned long long d;
    asm("fma.rn.f32x2 %0, %1, %2, %3;" : "=l"(d) : "l"(a), "l"(b), "l"(c));
    return d;
}

// Kernel 1: build EXg[h][i] = exp(-(x_i-x0_h)^2/(2 s^2)), EYg likewise.
__global__ void factor_kernel(const float* __restrict__ holes) {
    int idx = blockIdx.x * blockDim.x + threadIdx.x;
    if (idx >= NH * NN) return;
    int h = idx / NN;
    int i = idx - h * NN;
    float x0 = holes[h * 3 + 0];
    float y0 = holes[h * 3 + 1];
    float sg = holes[h * 3 + 2];
    float c  = -0.5f / (sg * sg);
    float xi = fmaf((float)i, 20.0f / 4000.0f, -10.0f);
    float dx = xi - x0;
    float dy = xi - y0;
    EXg[idx] = __expf(c * dx * dx);
    EYg[idx] = __expf(c * dy * dy);
}

// Kernel 2: rank-96 outer-product accumulation + sigmoid epilogue.
__global__ __launch_bounds__(NT2, 2)
void phc_kernel(const float* __restrict__ Tp, float* __restrict__ out) {
    extern __shared__ float smem[];
    float* sEX = smem;             // [NH][TILE]
    float* sEY = smem + NH * TILE; // [NH][TILE]

    const int tid = threadIdx.x;
    const int i0 = blockIdx.y * TILE;  // row (x) axis
    const int j0 = blockIdx.x * TILE;  // col (y) axis

    // prologue: pull factor slices from L2 (clamp edge so no NaNs; clamped
    // rows/cols are computed but never stored)
    for (int t = tid; t < NH * TILE; t += NT2) {
        int h  = t >> 7;
        int ii = t & (TILE - 1);
        int gi = min(i0 + ii, NN - 1);
        int gj = min(j0 + ii, NN - 1);
        sEX[t] = EXg[h * NN + gi];
        sEY[t] = EYg[h * NN + gj];
    }
    __syncthreads();

    // 8 rows x 4 cols per thread; 16 row-groups x 32 col-groups = 128x128
    const int tx = tid & 31;   // col group (lane) -> 4 cols
    const int ty = tid >> 5;   // row group (warp-uniform) -> 8 rows

    unsigned long long acc[8][2];
    #pragma unroll
    for (int r = 0; r < 8; ++r) { acc[r][0] = 0ull; acc[r][1] = 0ull; }

    const float* exB = sEX + ty * 8;  // warp-uniform address -> broadcast LDS
    const float* eyB = sEY + tx * 4;  // lane-sequential float4

    #pragma unroll 4
    for (int h = 0; h < NH; ++h) {
        float4 a0 = *(const float4*)(exB + h * TILE);
        float4 a1 = *(const float4*)(exB + h * TILE + 4);
        float4 b  = *(const float4*)(eyB + h * TILE);

        unsigned long long bp0 = pack2(b.x, b.y);
        unsigned long long bp1 = pack2(b.z, b.w);
        float ax[8] = {a0.x, a0.y, a0.z, a0.w, a1.x, a1.y, a1.z, a1.w};

        #pragma unroll
        for (int r = 0; r < 8; ++r) {
            unsigned long long ad = pack2(ax[r], ax[r]);
            acc[r][0] = fma2(ad, bp0, acc[r][0]);
            acc[r][1] = fma2(ad, bp1, acc[r][1]);
        }
    }

    // epilogue: sigmoid((Z-0.5)/T); scalar stores (row stride 4001 breaks
    // vector alignment). Lanes cover consecutive float4 chunks -> coalesced.
    const float invT = __fdividef(1.0f, Tp[0]);
    const int gj = j0 + tx * 4;

    #pragma unroll
    for (int r = 0; r < 8; ++r) {
        int gi = i0 + ty * 8 + r;
        if (gi >= NN) break;
        float z0, z1, z2, z3;
        unpack2(z0, z1, acc[r][0]);
        unpack2(z2, z3, acc[r][1]);
        float zz[4] = {z0, z1, z2, z3};
        float* orow = out + (size_t)gi * NN + gj;
        #pragma unroll
        for (int c = 0; c < 4; ++c) {
            if (gj + c < NN) {
                float e = __expf((0.5f - zz[c]) * invT);
                orow[c] = __fdividef(1.0f, 1.0f + e);
            }
        }
    }
}

extern "C" void kernel_launch(void* const* d_in, const int* in_sizes, int n_in,
                              void* d_out, int out_size) {
    const float* holes = (const float*)d_in[0];
    const float* T     = (const float*)d_in[1];
    float* out         = (float*)d_out;

    factor_kernel<<<(NH * NN + 255) / 256, 256>>>(holes);

    cudaFuncSetAttribute(phc_kernel,
                         cudaFuncAttributeMaxDynamicSharedMemorySize, SMEM_BYTES);
    dim3 grid((NN + TILE - 1) / TILE, (NN + TILE - 1) / TILE);
    phc_kernel<<<grid, NT2, SMEM_BYTES>>>(T, out);
}

// round 8
// speedup vs baseline: 1.4309x; 1.0702x over previous
#include <cuda_runtime.h>
#include <cstdint>

#define NN    4001
#define TILE  128
#define NH    96
#define NT2   512

// precomputed separable factors (worst-case 96 groups, 3 MB, L2-resident)
__device__ float EXg[NH * NN];
__device__ float EYg[NH * NN];
__device__ int   g_ng;          // number of distinct (y0, sigma) groups
__device__ int   g_map[NH];     // hole -> group

#define SMEM_FLOATS (2 * NH * TILE)
#define SMEM_BYTES  (SMEM_FLOATS * 4)

__device__ __forceinline__ unsigned long long pack2(float lo, float hi) {
    unsigned long long r;
    asm("mov.b64 %0, {%1, %2};" : "=l"(r) : "f"(lo), "f"(hi));
    return r;
}
__device__ __forceinline__ void unpack2(float& lo, float& hi, unsigned long long v) {
    asm("mov.b64 {%0, %1}, %2;" : "=f"(lo), "=f"(hi) : "l"(v));
}
__device__ __forceinline__ unsigned long long fma2(unsigned long long a,
                                                   unsigned long long b,
                                                   unsigned long long c) {
    unsigned long long d;
    asm("fma.rn.f32x2 %0, %1, %2, %3;" : "=l"(d) : "l"(a), "l"(b), "l"(c));
    return d;
}

// Kernel 0: group holes by identical (y0, sigma). Exact bit-equality: rows of
// the hole lattice are built from a single scalar per row, so equal profiles
// are bitwise equal. Worst case (all distinct): ng = NH -> graceful fallback.
__global__ void group_kernel(const float* __restrict__ holes) {
    if (blockIdx.x != 0 || threadIdx.x != 0) return;
    float ky[NH], ks[NH];
    int ng = 0;
    for (int h = 0; h < NH; ++h) {
        float y0 = holes[h * 3 + 1];
        float sg = holes[h * 3 + 2];
        int g = -1;
        for (int q = 0; q < ng; ++q)
            if (ky[q] == y0 && ks[q] == sg) { g = q; break; }
        if (g < 0) { g = ng; ky[ng] = y0; ks[ng] = sg; ng++; }
        g_map[h] = g;
    }
    g_ng = ng;
}

// Kernel 1: per group g:
//   EXg[g][i] = sum_{h in g} exp(-(x_i - x0_h)^2 / (2 s_h^2))
//   EYg[g][i] = exp(-(x_i - y0_g)^2 / (2 s_g^2))
__global__ void factor_kernel(const float* __restrict__ holes) {
    int idx = blockIdx.x * blockDim.x + threadIdx.x;
    if (idx >= NH * NN) return;
    int g = idx / NN;
    if (g >= g_ng) return;
    int i = idx - g * NN;

    float xi = fmaf((float)i, 20.0f / 4000.0f, -10.0f);
    float accx = 0.0f;
    float y0g = 0.0f, sgg = 1.0f;
    for (int h = 0; h < NH; ++h) {
        if (g_map[h] == g) {
            float x0 = holes[h * 3 + 0];
            float sg = holes[h * 3 + 2];
            float c  = -0.5f / (sg * sg);
            float dx = xi - x0;
            accx += __expf(c * dx * dx);
            y0g = holes[h * 3 + 1];
            sgg = sg;
        }
    }
    EXg[idx] = accx;
    float c  = -0.5f / (sgg * sgg);
    float dy = xi - y0g;
    EYg[idx] = __expf(c * dy * dy);
}

// Kernel 2: rank-ng outer-product accumulation + sigmoid epilogue.
__global__ __launch_bounds__(NT2, 2)
void phc_kernel(const float* __restrict__ Tp, float* __restrict__ out) {
    extern __shared__ float smem[];
    float* sEX = smem;             // [ng][TILE]
    float* sEY = smem + NH * TILE; // [ng][TILE]

    const int tid = threadIdx.x;
    const int i0 = blockIdx.y * TILE;  // row (x) axis
    const int j0 = blockIdx.x * TILE;  // col (y) axis
    const int ng = g_ng;

    // prologue: pull factor slices from L2 (edge-clamped; clamped lanes are
    // computed but never stored)
    for (int t = tid; t < ng * TILE; t += NT2) {
        int h  = t >> 7;
        int ii = t & (TILE - 1);
        int gi = min(i0 + ii, NN - 1);
        int gj = min(j0 + ii, NN - 1);
        sEX[t] = EXg[h * NN + gi];
        sEY[t] = EYg[h * NN + gj];
    }
    __syncthreads();

    // 8 rows x 4 cols per thread; 16 row-groups x 32 col-groups = 128x128
    const int tx = tid & 31;   // col group (lane) -> 4 cols
    const int ty = tid >> 5;   // row group (warp-uniform) -> 8 rows

    unsigned long long acc[8][2];
    #pragma unroll
    for (int r = 0; r < 8; ++r) { acc[r][0] = 0ull; acc[r][1] = 0ull; }

    const float* exB = sEX + ty * 8;  // warp-uniform -> broadcast LDS
    const float* eyB = sEY + tx * 4;  // lane-sequential float4

    #pragma unroll 2
    for (int h = 0; h < ng; ++h) {
        float4 a0 = *(const float4*)(exB + h * TILE);
        float4 a1 = *(const float4*)(exB + h * TILE + 4);
        float4 b  = *(const float4*)(eyB + h * TILE);

        unsigned long long bp0 = pack2(b.x, b.y);
        unsigned long long bp1 = pack2(b.z, b.w);
        float ax[8] = {a0.x, a0.y, a0.z, a0.w, a1.x, a1.y, a1.z, a1.w};

        #pragma unroll
        for (int r = 0; r < 8; ++r) {
            unsigned long long ad = pack2(ax[r], ax[r]);
            acc[r][0] = fma2(ad, bp0, acc[r][0]);
            acc[r][1] = fma2(ad, bp1, acc[r][1]);
        }
    }

    // epilogue: sigmoid((Z-0.5)/T); scalar stores (row stride 4001 breaks
    // vector alignment). Lanes cover consecutive float4 chunks -> coalesced.
    const float invT = __fdividef(1.0f, Tp[0]);
    const int gj = j0 + tx * 4;

    #pragma unroll
    for (int r = 0; r < 8; ++r) {
        int gi = i0 + ty * 8 + r;
        if (gi >= NN) break;
        float z0, z1, z2, z3;
        unpack2(z0, z1, acc[r][0]);
        unpack2(z2, z3, acc[r][1]);
        float zz[4] = {z0, z1, z2, z3};
        float* orow = out + (size_t)gi * NN + gj;
        #pragma unroll
        for (int c = 0; c < 4; ++c) {
            if (gj + c < NN) {
                float e = __expf((0.5f - zz[c]) * invT);
                orow[c] = __fdividef(1.0f, 1.0f + e);
            }
        }
    }
}

extern "C" void kernel_launch(void* const* d_in, const int* in_sizes, int n_in,
                              void* d_out, int out_size) {
    const float* holes = (const float*)d_in[0];
    const float* T     = (const float*)d_in[1];
    float* out         = (float*)d_out;

    group_kernel<<<1, 32>>>(holes);
    factor_kernel<<<(NH * NN + 255) / 256, 256>>>(holes);

    cudaFuncSetAttribute(phc_kernel,
                         cudaFuncAttributeMaxDynamicSharedMemorySize, SMEM_BYTES);
    dim3 grid((NN + TILE - 1) / TILE, (NN + TILE - 1) / TILE);
    phc_kernel<<<grid, NT2, SMEM_BYTES>>>(T, out);
}

// round 12
// speedup vs baseline: 1.8034x; 1.2603x over previous
#include <cuda_runtime.h>
#include <cstdint>

#define NN     4001
#define TILE_I 128
#define TILE_J 64
#define NH     96
#define MAXG   24
#define NT2    512

// precomputed separable factors (worst-case 96 groups, 3 MB, L2-resident)
__device__ float EXg[NH * NN];
__device__ float EYg[NH * NN];
__device__ int   g_ng;          // number of distinct (y0, sigma) groups
__device__ int   g_map[NH];     // hole -> group

#define SMEM_FLOATS (MAXG * TILE_I + MAXG * TILE_J)
#define SMEM_BYTES  (SMEM_FLOATS * 4)

__device__ __forceinline__ unsigned long long pack2(float lo, float hi) {
    unsigned long long r;
    asm("mov.b64 %0, {%1, %2};" : "=l"(r) : "f"(lo), "f"(hi));
    return r;
}
__device__ __forceinline__ void unpack2(float& lo, float& hi, unsigned long long v) {
    asm("mov.b64 {%0, %1}, %2;" : "=f"(lo), "=f"(hi) : "l"(v));
}
__device__ __forceinline__ unsigned long long fma2(unsigned long long a,
                                                   unsigned long long b,
                                                   unsigned long long c) {
    unsigned long long d;
    asm("fma.rn.f32x2 %0, %1, %2, %3;" : "=l"(d) : "l"(a), "l"(b), "l"(c));
    return d;
}
__device__ __forceinline__ float tanh_approx(float x) {
    float y; asm("tanh.approx.f32 %0, %1;" : "=f"(y) : "f"(x)); return y;
}

// Kernel 0: group holes by identical (y0, sigma), parallel over holes.
// Exact bit-equality is valid: each lattice row's profile is built from one
// scalar, so equal profiles are bitwise equal. Worst case ng = NH (fallback).
__global__ void group_kernel(const float* __restrict__ holes) {
    __shared__ float sy[NH], ss[NH];
    __shared__ int leader[NH], firsts[NH], gid[NH];
    int h = threadIdx.x;
    if (h < NH) { sy[h] = holes[h * 3 + 1]; ss[h] = holes[h * 3 + 2]; }
    __syncthreads();
    if (h < NH) {
        int f = h;
        for (int q = 0; q < h; ++q)
            if (sy[q] == sy[h] && ss[q] == ss[h]) { f = q; break; }
        firsts[h] = f;
        leader[h] = (f == h) ? 1 : 0;
    }
    __syncthreads();
    if (h == 0) {
        int ng = 0;
        for (int q = 0; q < NH; ++q) { gid[q] = ng; if (leader[q]) ng++; }
        g_ng = ng;
    }
    __syncthreads();
    if (h < NH) g_map[h] = gid[firsts[h]];
}

// Kernel 1: per group g:
//   EXg[g][i] = sum_{h in g} exp(-(x_i - x0_h)^2 / (2 s_h^2))
//   EYg[g][i] = exp(-(x_i - y0_g)^2 / (2 s_g^2))
__global__ void factor_kernel(const float* __restrict__ holes) {
    int idx = blockIdx.x * blockDim.x + threadIdx.x;
    if (idx >= NH * NN) return;
    int g = idx / NN;
    if (g >= g_ng) return;
    int i = idx - g * NN;

    float xi = fmaf((float)i, 20.0f / 4000.0f, -10.0f);
    float accx = 0.0f;
    float y0g = 0.0f, sgg = 1.0f;
    for (int h = 0; h < NH; ++h) {
        if (g_map[h] == g) {
            float x0 = holes[h * 3 + 0];
            float sg = holes[h * 3 + 2];
            float c  = -0.5f / (sg * sg);
            float dx = xi - x0;
            accx += __expf(c * dx * dx);
            y0g = holes[h * 3 + 1];
            sgg = sg;
        }
    }
    EXg[idx] = accx;
    float c  = -0.5f / (sgg * sgg);
    float dy = xi - y0g;
    EYg[idx] = __expf(c * dy * dy);
}

// Kernel 2: rank-ng outer-product accumulation + sigmoid epilogue.
// 128x64 tile per CTA; 8 rows x 2 cols per thread (16 f32 accumulators).
// Groups processed in chunks of MAXG through an 18KB smem window so
// occupancy is register-limited, not smem-limited.
__global__ __launch_bounds__(NT2, 3)
void phc_kernel(const float* __restrict__ Tp, float* __restrict__ out) {
    extern __shared__ float smem[];
    float* sEX = smem;                  // [MAXG][TILE_I]
    float* sEY = smem + MAXG * TILE_I;  // [MAXG][TILE_J]

    const int tid = threadIdx.x;
    const int i0 = blockIdx.y * TILE_I;  // row (x) axis
    const int j0 = blockIdx.x * TILE_J;  // col (y) axis
    const int ng = g_ng;

    const int tx = tid & 31;   // lane -> 2 cols
    const int ty = tid >> 5;   // warp (uniform) -> 8 rows

    unsigned long long acc[8];
    #pragma unroll
    for (int r = 0; r < 8; ++r) acc[r] = 0ull;

    const float* exB = sEX + ty * 8;  // warp-uniform -> broadcast LDS
    const float* eyB = sEY + tx * 2;  // lane-sequential float2

    for (int c0 = 0; c0 < ng; c0 += MAXG) {
        const int nc = min(MAXG, ng - c0);
        __syncthreads();   // previous chunk fully consumed
        // stage chunk from L2 (edge-clamped; clamped lanes never stored)
        const int tot = nc * (TILE_I + TILE_J);
        for (int t = tid; t < tot; t += NT2) {
            if (t < nc * TILE_I) {
                int g  = t >> 7;
                int ii = t & (TILE_I - 1);
                sEX[g * TILE_I + ii] = EXg[(c0 + g) * NN + min(i0 + ii, NN - 1)];
            } else {
                int u  = t - nc * TILE_I;
                int g  = u >> 6;
                int jj = u & (TILE_J - 1);
                sEY[g * TILE_J + jj] = EYg[(c0 + g) * NN + min(j0 + jj, NN - 1)];
            }
        }
        __syncthreads();

        for (int h = 0; h < nc; ++h) {
            float4 a0 = *(const float4*)(exB + h * TILE_I);
            float4 a1 = *(const float4*)(exB + h * TILE_I + 4);
            float2 b  = *(const float2*)(eyB + h * TILE_J);
            unsigned long long bp = pack2(b.x, b.y);
            float ax[8] = {a0.x, a0.y, a0.z, a0.w, a1.x, a1.y, a1.z, a1.w};
            #pragma unroll
            for (int r = 0; r < 8; ++r)
                acc[r] = fma2(pack2(ax[r], ax[r]), bp, acc[r]);
        }
    }

    // epilogue: sigmoid((Z-0.5)/T) = 0.5*tanh((Z-0.5)/(2T)) + 0.5
    const float hInvT = 0.5f * __fdividef(1.0f, Tp[0]);
    const int gj = j0 + tx * 2;

    #pragma unroll
    for (int r = 0; r < 8; ++r) {
        int gi = i0 + ty * 8 + r;
        if (gi >= NN) break;
        float z0, z1;
        unpack2(z0, z1, acc[r]);
        float* orow = out + (size_t)gi * NN + gj;
        float s0 = fmaf(0.5f, tanh_approx((z0 - 0.5f) * hInvT), 0.5f);
        float s1 = fmaf(0.5f, tanh_approx((z1 - 0.5f) * hInvT), 0.5f);
        if (gj < NN)     orow[0] = s0;
        if (gj + 1 < NN) orow[1] = s1;
    }
}

extern "C" void kernel_launch(void* const* d_in, const int* in_sizes, int n_in,
                              void* d_out, int out_size) {
    const float* holes = (const float*)d_in[0];
    const float* T     = (const float*)d_in[1];
    float* out         = (float*)d_out;

    group_kernel<<<1, 128>>>(holes);
    factor_kernel<<<(NH * NN + 255) / 256, 256>>>(holes);

    cudaFuncSetAttribute(phc_kernel,
                         cudaFuncAttributeMaxDynamicSharedMemorySize, SMEM_BYTES);
    dim3 grid((NN + TILE_J - 1) / TILE_J, (NN + TILE_I - 1) / TILE_I);
    phc_kernel<<<grid, NT2, SMEM_BYTES>>>(T, out);
}

// round 15
// speedup vs baseline: 2.3866x; 1.3234x over previous
#include <cuda_runtime.h>
#include <cstdint>

#define NN     4001
#define TILE_I 128
#define TILE_J 64
#define NH     96
#define MAXG   24
#define NT2    512

// precomputed separable factors (worst-case 96 groups, 3 MB, L2-resident)
__device__ float EXg[NH * NN];
__device__ float EYg[NH * NN];
__device__ int   g_ng;          // number of distinct (y0, sigma) groups

#define SMEM_FLOATS (MAXG * TILE_I + MAXG * TILE_J)
#define SMEM_BYTES  (SMEM_FLOATS * 4)

__device__ __forceinline__ unsigned long long pack2(float lo, float hi) {
    unsigned long long r;
    asm("mov.b64 %0, {%1, %2};" : "=l"(r) : "f"(lo), "f"(hi));
    return r;
}
__device__ __forceinline__ void unpack2(float& lo, float& hi, unsigned long long v) {
    asm("mov.b64 {%0, %1}, %2;" : "=f"(lo), "=f"(hi) : "l"(v));
}
__device__ __forceinline__ unsigned long long fma2(unsigned long long a,
                                                   unsigned long long b,
                                                   unsigned long long c) {
    unsigned long long d;
    asm("fma.rn.f32x2 %0, %1, %2, %3;" : "=l"(d) : "l"(a), "l"(b), "l"(c));
    return d;
}
__device__ __forceinline__ float tanh_approx(float x) {
    float y; asm("tanh.approx.f32 %0, %1;" : "=f"(y) : "f"(x)); return y;
}

// Kernel 1: grouping (redundant per CTA, fully parallel, no serial chains)
// + factor build:
//   EXg[g][i] = sum_{h in g} exp(-(x_i - x0_h)^2 / (2 s_h^2))
//   EYg[g][i] = exp(-(x_i - y0_g)^2 / (2 s_g^2))
// Groups = identical (y0, sigma); bit-equality valid (each lattice row's
// profile built from one scalar). Worst case ng = NH -> graceful fallback.
__global__ __launch_bounds__(256)
void factor_kernel(const float* __restrict__ holes) {
    __shared__ float sy[NH], ss[NH];
    __shared__ int   smap[NH];
    __shared__ unsigned wmask[NH / 32];
    __shared__ int   s_ng;

    const int t = threadIdx.x;
    if (t < NH) { sy[t] = holes[t * 3 + 1]; ss[t] = holes[t * 3 + 2]; }
    __syncthreads();

    if (t < NH) {  // exactly warps 0..2, all lanes active
        // first index with matching profile (break-free -> loads overlap)
        int f = t;
        #pragma unroll 8
        for (int q = 0; q < NH; ++q) {
            bool m = (q < f) && (sy[q] == sy[t]) && (ss[q] == ss[t]);
            if (m) f = q;
        }
        unsigned lead = __ballot_sync(0xFFFFFFFFu, f == t);
        if ((t & 31) == 0) wmask[t >> 5] = lead;
        __syncwarp();
    }
    __syncthreads();
    if (t < NH) {
        // recompute f (cheap) to index the prefix
        int f = t;
        #pragma unroll 8
        for (int q = 0; q < NH; ++q) {
            bool m = (q < f) && (sy[q] == sy[t]) && (ss[q] == ss[t]);
            if (m) f = q;
        }
        int wf = f >> 5, bf = f & 31;
        int cnt = 0;
        #pragma unroll
        for (int w = 0; w < NH / 32; ++w)
            cnt += (w < wf) ? __popc(wmask[w])
                 : (w == wf ? __popc(wmask[w] & ((1u << bf) - 1u)) : 0);
        smap[t] = cnt;   // group id = #leaders strictly before f (f is a leader)
        if (t == 0) {
            int ng = 0;
            #pragma unroll
            for (int w = 0; w < NH / 32; ++w) ng += __popc(wmask[w]);
            s_ng = ng;
            if (blockIdx.x == 0) g_ng = ng;
        }
    }
    __syncthreads();

    const int ng  = s_ng;
    int idx = blockIdx.x * blockDim.x + t;
    if (idx >= NH * NN) return;
    int g = idx / NN;
    if (g >= ng) return;
    int i = idx - g * NN;

    float xi = fmaf((float)i, 20.0f / 4000.0f, -10.0f);
    float accx = 0.0f;
    float y0g = 0.0f, sgg = 1.0f;
    for (int h = 0; h < NH; ++h) {
        if (smap[h] == g) {
            float x0 = holes[h * 3 + 0];
            float sg = ss[h];
            float c  = -0.5f / (sg * sg);
            float dx = xi - x0;
            accx += __expf(c * dx * dx);
            y0g = sy[h];
            sgg = sg;
        }
    }
    EXg[idx] = accx;
    float c  = -0.5f / (sgg * sgg);
    float dy = xi - y0g;
    EYg[idx] = __expf(c * dy * dy);
}

// Kernel 2: rank-ng outer-product accumulation + sigmoid epilogue.
// 128x64 tile per CTA; 8 rows x 2 cols per thread.
// Row-pair packing: acc[p][c] = (Z[2p][c], Z[2p+1][c]); the 'a' operand pairs
// come straight out of LDS.128 (no dup-pack MOVs), only 'b' is duplicated.
__global__ __launch_bounds__(NT2, 3)
void phc_kernel(const float* __restrict__ Tp, float* __restrict__ out) {
    extern __shared__ float smem[];
    float* sEX = smem;                  // [MAXG][TILE_I]
    float* sEY = smem + MAXG * TILE_I;  // [MAXG][TILE_J]

    const int tid = threadIdx.x;
    const int i0 = blockIdx.y * TILE_I;  // row (x) axis
    const int j0 = blockIdx.x * TILE_J;  // col (y) axis
    const int ng = g_ng;

    const int tx = tid & 31;   // lane -> 2 cols
    const int ty = tid >> 5;   // warp (uniform) -> 8 rows

    unsigned long long acc[4][2];
    #pragma unroll
    for (int p = 0; p < 4; ++p) { acc[p][0] = 0ull; acc[p][1] = 0ull; }

    const float* exB = sEX + ty * 8;  // warp-uniform -> broadcast LDS
    const float* eyB = sEY + tx * 2;  // lane-sequential float2

    for (int c0 = 0; c0 < ng; c0 += MAXG) {
        const int nc = min(MAXG, ng - c0);
        __syncthreads();   // previous chunk fully consumed
        // stage chunk from L2 (edge-clamped; clamped lanes never stored)
        const int tot = nc * (TILE_I + TILE_J);
        for (int t = tid; t < tot; t += NT2) {
            if (t < nc * TILE_I) {
                int g  = t >> 7;
                int ii = t & (TILE_I - 1);
                sEX[g * TILE_I + ii] = EXg[(c0 + g) * NN + min(i0 + ii, NN - 1)];
            } else {
                int u  = t - nc * TILE_I;
                int g  = u >> 6;
                int jj = u & (TILE_J - 1);
                sEY[g * TILE_J + jj] = EYg[(c0 + g) * NN + min(j0 + jj, NN - 1)];
            }
        }
        __syncthreads();

        for (int h = 0; h < nc; ++h) {
            ulonglong2 aA = *(const ulonglong2*)(exB + h * TILE_I);      // rows 0..3
            ulonglong2 aB = *(const ulonglong2*)(exB + h * TILE_I + 4);  // rows 4..7
            float2 b = *(const float2*)(eyB + h * TILE_J);
            unsigned long long b0 = pack2(b.x, b.x);
            unsigned long long b1 = pack2(b.y, b.y);
            acc[0][0] = fma2(aA.x, b0, acc[0][0]);
            acc[0][1] = fma2(aA.x, b1, acc[0][1]);
            acc[1][0] = fma2(aA.y, b0, acc[1][0]);
            acc[1][1] = fma2(aA.y, b1, acc[1][1]);
            acc[2][0] = fma2(aB.x, b0, acc[2][0]);
            acc[2][1] = fma2(aB.x, b1, acc[2][1]);
            acc[3][0] = fma2(aB.y, b0, acc[3][0]);
            acc[3][1] = fma2(aB.y, b1, acc[3][1]);
        }
    }

    // epilogue: sigmoid((Z-0.5)/T) = 0.5*tanh((Z-0.5)/(2T)) + 0.5
    const float hInvT = 0.5f * __fdividef(1.0f, Tp[0]);
    const int gj = j0 + tx * 2;

    #pragma unroll
    for (int p = 0; p < 4; ++p) {
        float z0c0, z1c0, z0c1, z1c1;
        unpack2(z0c0, z1c0, acc[p][0]);   // col 0: rows 2p, 2p+1
        unpack2(z0c1, z1c1, acc[p][1]);   // col 1
        int gi = i0 + ty * 8 + 2 * p;
        #pragma unroll
        for (int rr = 0; rr < 2; ++rr) {
            int g = gi + rr;
            if (g >= NN) break;
            float za = rr ? z1c0 : z0c0;
            float zb = rr ? z1c1 : z0c1;
            float* orow = out + (size_t)g * NN + gj;
            float s0 = fmaf(0.5f, tanh_approx((za - 0.5f) * hInvT), 0.5f);
            float s1 = fmaf(0.5f, tanh_approx((zb - 0.5f) * hInvT), 0.5f);
            if (gj < NN)     orow[0] = s0;
            if (gj + 1 < NN) orow[1] = s1;
        }
    }
}

extern "C" void kernel_launch(void* const* d_in, const int* in_sizes, int n_in,
                              void* d_out, int out_size) {
    const float* holes = (const float*)d_in[0];
    const float* T     = (const float*)d_in[1];
    float* out         = (float*)d_out;

    factor_kernel<<<(NH * NN + 255) / 256, 256>>>(holes);

    cudaFuncSetAttribute(phc_kernel,
                         cudaFuncAttributeMaxDynamicSharedMemorySize, SMEM_BYTES);
    dim3 grid((NN + TILE_J - 1) / TILE_J, (NN + TILE_I - 1) / TILE_I);
    phc_kernel<<<grid, NT2, SMEM_BYTES>>>(T, out);
}

// round 17
// speedup vs baseline: 3.3351x; 1.3974x over previous
#include <cuda_runtime.h>
#include <cstdint>

#define NN     4001
#define TILE_I 128
#define TILE_J 64
#define NH     96
#define MAXG   24
#define NT2    512

// precomputed separable factors (worst-case 96 groups, 3 MB, L2-resident)
__device__ float EXg[NH * NN];
__device__ float EYg[NH * NN];
__device__ int   g_ng;             // number of distinct (y0, sigma) groups
__device__ int   g_cnt[NH];        // members per group
__device__ int   g_memb[NH * NH];  // [g][k] -> hole index
__device__ float g_y0[NH], g_sg[NH];

#define SMEM_FLOATS (MAXG * TILE_I + MAXG * TILE_J)
#define SMEM_BYTES  (SMEM_FLOATS * 4)

__device__ __forceinline__ unsigned long long pack2(float lo, float hi) {
    unsigned long long r;
    asm("mov.b64 %0, {%1, %2};" : "=l"(r) : "f"(lo), "f"(hi));
    return r;
}
__device__ __forceinline__ void unpack2(float& lo, float& hi, unsigned long long v) {
    asm("mov.b64 {%0, %1}, %2;" : "=f"(lo), "=f"(hi) : "l"(v));
}
__device__ __forceinline__ unsigned long long fma2(unsigned long long a,
                                                   unsigned long long b,
                                                   unsigned long long c) {
    unsigned long long d;
    asm("fma.rn.f32x2 %0, %1, %2, %3;" : "=l"(d) : "l"(a), "l"(b), "l"(c));
    return d;
}
__device__ __forceinline__ float tanh_approx(float x) {
    float y; asm("tanh.approx.f32 %0, %1;" : "=f"(y) : "f"(x)); return y;
}

// Kernel 0 (1 CTA, parallel, no serial chains): group holes by identical
// (y0, sigma) via ballot+popc prefix; leaders build ordered member lists.
// Bit-equality is valid (each lattice row's profile built from one scalar).
// Worst case ng = NH -> graceful fallback.
__global__ void group_kernel(const float* __restrict__ holes) {
    __shared__ float sy[NH], ss[NH];
    __shared__ int   smap[NH];
    __shared__ unsigned wmask[NH / 32];

    const int t = threadIdx.x;
    if (t < NH) { sy[t] = holes[t * 3 + 1]; ss[t] = holes[t * 3 + 2]; }
    __syncthreads();

    int f = t;
    if (t < NH) {  // exactly warps 0..2, all lanes active
        #pragma unroll 8
        for (int q = 0; q < NH; ++q) {
            bool m = (q < f) && (sy[q] == sy[t]) && (ss[q] == ss[t]);
            if (m) f = q;
        }
        unsigned lead = __ballot_sync(0xFFFFFFFFu, f == t);
        if ((t & 31) == 0) wmask[t >> 5] = lead;
    }
    __syncthreads();
    if (t < NH) {
        int wf = f >> 5, bf = f & 31;
        int cnt = 0;
        #pragma unroll
        for (int w = 0; w < NH / 32; ++w)
            cnt += (w < wf) ? __popc(wmask[w])
                 : (w == wf ? __popc(wmask[w] & ((1u << bf) - 1u)) : 0);
        smap[t] = cnt;   // group id = #leaders strictly before f
        if (t == 0) {
            int ng = 0;
            #pragma unroll
            for (int w = 0; w < NH / 32; ++w) ng += __popc(wmask[w]);
            g_ng = ng;
        }
    }
    __syncthreads();
    if (t < NH && f == t) {      // leaders (<= ng threads) build member lists
        int g = smap[t];
        int k = 0;
        for (int h = 0; h < NH; ++h)
            if (smap[h] == g) g_memb[g * NH + (k++)] = h;
        g_cnt[g] = k;
        g_y0[g]  = sy[t];
        g_sg[g]  = ss[t];
    }
}

// Kernel 1: per group g (member lists precomputed):
//   EXg[g][i] = sum_{h in g} exp(-(x_i - x0_h)^2 / (2 s^2))
//   EYg[g][i] = exp(-(x_i - y0_g)^2 / (2 s^2))
__global__ __launch_bounds__(256)
void factor_kernel(const float* __restrict__ holes) {
    int idx = blockIdx.x * blockDim.x + threadIdx.x;
    if (idx >= NH * NN) return;
    int g = idx / NN;
    if (g >= g_ng) return;
    int i = idx - g * NN;

    float sg = g_sg[g];
    float c  = -0.5f * __fdividef(1.0f, sg * sg);
    float xi = fmaf((float)i, 20.0f / 4000.0f, -10.0f);

    float accx = 0.0f;
    const int cnt = g_cnt[g];
    const int* mem = g_memb + g * NH;
    for (int k = 0; k < cnt; ++k) {
        float x0 = holes[mem[k] * 3 + 0];
        float dx = xi - x0;
        accx += __expf(c * dx * dx);
    }
    EXg[idx] = accx;
    float dy = xi - g_y0[g];
    EYg[idx] = __expf(c * dy * dy);
}

// Kernel 2: rank-ng outer-product accumulation + sigmoid epilogue.
// 128x64 tile per CTA; 8 rows x 2 cols per thread.
// Row-pair packing: 'a' operand pairs come straight out of LDS.128 (no
// dup-pack MOVs), only 'b' is duplicated.
__global__ __launch_bounds__(NT2, 3)
void phc_kernel(const float* __restrict__ Tp, float* __restrict__ out) {
    extern __shared__ float smem[];
    float* sEX = smem;                  // [MAXG][TILE_I]
    float* sEY = smem + MAXG * TILE_I;  // [MAXG][TILE_J]

    const int tid = threadIdx.x;
    const int i0 = blockIdx.y * TILE_I;  // row (x) axis
    const int j0 = blockIdx.x * TILE_J;  // col (y) axis
    const int ng = g_ng;

    const int tx = tid & 31;   // lane -> 2 cols
    const int ty = tid >> 5;   // warp (uniform) -> 8 rows

    unsigned long long acc[4][2];
    #pragma unroll
    for (int p = 0; p < 4; ++p) { acc[p][0] = 0ull; acc[p][1] = 0ull; }

    const float* exB = sEX + ty * 8;  // warp-uniform -> broadcast LDS
    const float* eyB = sEY + tx * 2;  // lane-sequential float2

    for (int c0 = 0; c0 < ng; c0 += MAXG) {
        const int nc = min(MAXG, ng - c0);
        __syncthreads();   // previous chunk fully consumed
        // stage chunk from L2 (edge-clamped; clamped lanes never stored)
        const int tot = nc * (TILE_I + TILE_J);
        for (int t = tid; t < tot; t += NT2) {
            if (t < nc * TILE_I) {
                int g  = t >> 7;
                int ii = t & (TILE_I - 1);
                sEX[g * TILE_I + ii] = EXg[(c0 + g) * NN + min(i0 + ii, NN - 1)];
            } else {
                int u  = t - nc * TILE_I;
                int g  = u >> 6;
                int jj = u & (TILE_J - 1);
                sEY[g * TILE_J + jj] = EYg[(c0 + g) * NN + min(j0 + jj, NN - 1)];
            }
        }
        __syncthreads();

        for (int h = 0; h < nc; ++h) {
            ulonglong2 aA = *(const ulonglong2*)(exB + h * TILE_I);      // rows 0..3
            ulonglong2 aB = *(const ulonglong2*)(exB + h * TILE_I + 4);  // rows 4..7
            float2 b = *(const float2*)(eyB + h * TILE_J);
            unsigned long long b0 = pack2(b.x, b.x);
            unsigned long long b1 = pack2(b.y, b.y);
            acc[0][0] = fma2(aA.x, b0, acc[0][0]);
            acc[0][1] = fma2(aA.x, b1, acc[0][1]);
            acc[1][0] = fma2(aA.y, b0, acc[1][0]);
            acc[1][1] = fma2(aA.y, b1, acc[1][1]);
            acc[2][0] = fma2(aB.x, b0, acc[2][0]);
            acc[2][1] = fma2(aB.x, b1, acc[2][1]);
            acc[3][0] = fma2(aB.y, b0, acc[3][0]);
            acc[3][1] = fma2(aB.y, b1, acc[3][1]);
        }
    }

    // epilogue: sigmoid((Z-0.5)/T) = 0.5*tanh((Z-0.5)/(2T)) + 0.5
    const float hInvT = 0.5f * __fdividef(1.0f, Tp[0]);
    const int gj = j0 + tx * 2;

    #pragma unroll
    for (int p = 0; p < 4; ++p) {
        float z0c0, z1c0, z0c1, z1c1;
        unpack2(z0c0, z1c0, acc[p][0]);   // col 0: rows 2p, 2p+1
        unpack2(z0c1, z1c1, acc[p][1]);   // col 1
        int gi = i0 + ty * 8 + 2 * p;
        #pragma unroll
        for (int rr = 0; rr < 2; ++rr) {
            int g = gi + rr;
            if (g >= NN) break;
            float za = rr ? z1c0 : z0c0;
            float zb = rr ? z1c1 : z0c1;
            float* orow = out + (size_t)g * NN + gj;
            float s0 = fmaf(0.5f, tanh_approx((za - 0.5f) * hInvT), 0.5f);
            float s1 = fmaf(0.5f, tanh_approx((zb - 0.5f) * hInvT), 0.5f);
            if (gj < NN)     orow[0] = s0;
            if (gj + 1 < NN) orow[1] = s1;
        }
    }
}

extern "C" void kernel_launch(void* const* d_in, const int* in_sizes, int n_in,
                              void* d_out, int out_size) {
    const float* holes = (const float*)d_in[0];
    const float* T     = (const float*)d_in[1];
    float* out         = (float*)d_out;

    group_kernel<<<1, 128>>>(holes);
    factor_kernel<<<(NH * NN + 255) / 256, 256>>>(holes);

    cudaFuncSetAttribute(phc_kernel,
                         cudaFuncAttributeMaxDynamicSharedMemorySize, SMEM_BYTES);
    dim3 grid((NN + TILE_J - 1) / TILE_J, (NN + TILE_I - 1) / TILE_I);
    phc_kernel<<<grid, NT2, SMEM_BYTES>>>(T, out);
}